// round 2
// baseline (speedup 1.0000x reference)
#include <cuda_runtime.h>

// Problem constants
#define E        30          // elements per cell (B*5 + C = 2*5 + 20)
#define CELLS    802816      // 16384 * 7 * 7
#define CPB      128         // cells per block
#define THREADS  256

__global__ void zero_out_kernel(float* out, int n) {
    int i = threadIdx.x;
    if (i < n) out[i] = 0.0f;
}

__global__ __launch_bounds__(THREADS)
void yolo_loss_kernel(const float* __restrict__ pred,
                      const float* __restrict__ tgt,
                      float* __restrict__ out) {
    __shared__ float sp[CPB * E];
    __shared__ float st[CPB * E];
    __shared__ float red[THREADS / 32][5];

    const int tid = threadIdx.x;
    const long long base = (long long)blockIdx.x * (CPB * E);

    // ---- Stage 128 cells of both tensors into smem, coalesced float4 ----
    // CPB*E = 3840 floats = 960 float4 per tensor; 16B-aligned since
    // base bytes = blockIdx * 15360 (multiple of 16).
    const float4* gp = (const float4*)(pred + base);
    const float4* gt = (const float4*)(tgt  + base);
    float4* s4p = (float4*)sp;
    float4* s4t = (float4*)st;
    #pragma unroll
    for (int i = tid; i < (CPB * E) / 4; i += THREADS) {
        s4p[i] = gp[i];
        s4t[i] = gt[i];
    }
    __syncthreads();

    float lxy = 0.f, lwh = 0.f, lobj = 0.f, lnoobj = 0.f, lcls = 0.f;

    if (tid < CPB) {
        const float* p = sp + tid * E;
        const float* g = st + tid * E;

        const float conf = g[4];
        const float m  = (conf > 0.0f)  ? 1.0f : 0.0f;
        const float nm = (conf == 0.0f) ? 1.0f : 0.0f;

        // IoU of both pred boxes vs FIRST target box
        const float t0x = g[0], t0y = g[1], t0X = g[2], t0Y = g[3];
        const float a2 = (t0X - t0x) * (t0Y - t0y);

        float iou[2];
        #pragma unroll
        for (int b = 0; b < 2; b++) {
            const float* pb = p + b * 5;
            float ltx = fmaxf(pb[0], t0x);
            float lty = fmaxf(pb[1], t0y);
            float rbx = fminf(pb[2], t0X);
            float rby = fminf(pb[3], t0Y);
            float w = fmaxf(rbx - ltx, 0.0f);
            float h = fmaxf(rby - lty, 0.0f);
            float inter = w * h;
            float a1 = (pb[2] - pb[0]) * (pb[3] - pb[1]);
            iou[b] = inter / (a1 + a2 - inter);
        }

        // jnp.argmax takes the FIRST max on ties -> strict '>' for box 1
        const int best = (iou[1] > iou[0]) ? 1 : 0;
        const float maxiou = iou[best];

        const float* pb = p + best * 5;
        const float* tb = g + best * 5;

        // xy loss
        const float dx = pb[0] - tb[0];
        const float dy = pb[1] - tb[1];
        lxy = m * (dx * dx + dy * dy);

        // wh loss (sqrt space)
        const float dw = sqrtf(pb[2]) - sqrtf(tb[2]);
        const float dh = sqrtf(pb[3]) - sqrtf(tb[3]);
        lwh = m * (dw * dw + dh * dh);

        // objectness loss
        const float dobj = pb[4] - maxiou;
        lobj = m * dobj * dobj;

        // no-object loss (channels 4 and 9)
        const float d4 = p[4] - g[4];
        const float d9 = p[9] - g[9];
        lnoobj = nm * (d4 * d4 + d9 * d9);

        // class loss (channels 10..29)
        float cs = 0.0f;
        #pragma unroll
        for (int c = 10; c < 30; c++) {
            const float d = p[c] - g[c];
            cs += d * d;
        }
        lcls = m * cs;
    }

    // ---- Block reduction of 5 partials ----
    #pragma unroll
    for (int o = 16; o > 0; o >>= 1) {
        lxy    += __shfl_down_sync(0xffffffffu, lxy,    o);
        lwh    += __shfl_down_sync(0xffffffffu, lwh,    o);
        lobj   += __shfl_down_sync(0xffffffffu, lobj,   o);
        lnoobj += __shfl_down_sync(0xffffffffu, lnoobj, o);
        lcls   += __shfl_down_sync(0xffffffffu, lcls,   o);
    }
    const int wid  = tid >> 5;
    const int lane = tid & 31;
    if (lane == 0) {
        red[wid][0] = lxy;
        red[wid][1] = lwh;
        red[wid][2] = lobj;
        red[wid][3] = lnoobj;
        red[wid][4] = lcls;
    }
    __syncthreads();
    if (tid < 5) {
        float s = 0.0f;
        #pragma unroll
        for (int w = 0; w < THREADS / 32; w++) s += red[w][tid];
        atomicAdd(out + tid, s);
    }
}

extern "C" void kernel_launch(void* const* d_in, const int* in_sizes, int n_in,
                              void* d_out, int out_size) {
    const float* pred = (const float*)d_in[0];
    const float* tgt  = (const float*)d_in[1];
    float* out = (float*)d_out;

    zero_out_kernel<<<1, 32>>>(out, out_size);
    yolo_loss_kernel<<<CELLS / CPB, THREADS>>>(pred, tgt, out);
}

// round 3
// speedup vs baseline: 1.1599x; 1.1599x over previous
#include <cuda_runtime.h>
#include <cstdint>

// Problem constants
#define E           30                 // channels per cell (B*5 + C)
#define CELLS       802816             // 16384 * 7 * 7
#define CPB         128                // cells per block
#define THREADS     128
#define TILE_FLOATS (CPB * E)          // 3840
#define TILE_BYTES  (TILE_FLOATS * 4)  // 15360

__device__ __forceinline__ uint32_t smem_u32(const void* p) {
    uint32_t a;
    asm("{ .reg .u64 t; cvta.to.shared.u64 t, %1; cvt.u32.u64 %0, t; }"
        : "=r"(a) : "l"(p));
    return a;
}

__global__ __launch_bounds__(THREADS)
void yolo_loss_kernel(const float* __restrict__ pred,
                      const float* __restrict__ tgt,
                      float* __restrict__ out) {
    __shared__ __align__(16) float sp[TILE_FLOATS];
    __shared__ __align__(16) float st[TILE_FLOATS];
    __shared__ __align__(8)  uint64_t mbar;
    __shared__ float red[THREADS / 32][5];

    const int tid = threadIdx.x;
    const long long base = (long long)blockIdx.x * TILE_FLOATS;

    const uint32_t mbar_a = smem_u32(&mbar);

    if (tid == 0) {
        asm volatile("mbarrier.init.shared.b64 [%0], %1;"
                     :: "r"(mbar_a), "r"(1) : "memory");
    }
    __syncthreads();

    if (tid == 0) {
        asm volatile("mbarrier.arrive.expect_tx.shared.b64 _, [%0], %1;"
                     :: "r"(mbar_a), "r"(2 * TILE_BYTES) : "memory");
        // Bulk async copies: GMEM -> SMEM, 15360 B each (16B aligned both sides).
        asm volatile(
            "cp.async.bulk.shared::cta.global.mbarrier::complete_tx::bytes "
            "[%0], [%1], %2, [%3];"
            :: "r"(smem_u32(sp)), "l"(pred + base), "r"(TILE_BYTES), "r"(mbar_a)
            : "memory");
        asm volatile(
            "cp.async.bulk.shared::cta.global.mbarrier::complete_tx::bytes "
            "[%0], [%1], %2, [%3];"
            :: "r"(smem_u32(st)), "l"(tgt + base), "r"(TILE_BYTES), "r"(mbar_a)
            : "memory");
    }

    // Wait for both TMA copies (phase parity 0), acquire ordering for the LDS below.
    {
        uint32_t done;
        asm volatile(
            "{\n\t"
            ".reg .pred p;\n\t"
            "mbarrier.try_wait.parity.acquire.cta.shared::cta.b64 p, [%1], %2;\n\t"
            "selp.b32 %0, 1, 0, p;\n\t"
            "}"
            : "=r"(done) : "r"(mbar_a), "r"(0) : "memory");
        if (!done) {
            asm volatile(
                "{\n\t"
                ".reg .pred P1;\n\t"
                "WAIT_LOOP_%=:\n\t"
                "mbarrier.try_wait.parity.acquire.cta.shared::cta.b64 P1, [%0], %1, 0x989680;\n\t"
                "@P1 bra.uni WAIT_DONE_%=;\n\t"
                "bra.uni WAIT_LOOP_%=;\n\t"
                "WAIT_DONE_%=:\n\t"
                "}"
                :: "r"(mbar_a), "r"(0) : "memory");
        }
    }

    // ---- Per-thread cell compute (all 128 threads active) ----
    const float* p = sp + tid * E;
    const float* g = st + tid * E;

    const float conf = g[4];
    const float m  = (conf > 0.0f)  ? 1.0f : 0.0f;
    const float nm = (conf == 0.0f) ? 1.0f : 0.0f;

    // IoU of both pred boxes vs FIRST target box
    const float t0x = g[0], t0y = g[1], t0X = g[2], t0Y = g[3];
    const float a2 = (t0X - t0x) * (t0Y - t0y);

    float iou[2];
    #pragma unroll
    for (int b = 0; b < 2; b++) {
        const float* pb = p + b * 5;
        float ltx = fmaxf(pb[0], t0x);
        float lty = fmaxf(pb[1], t0y);
        float rbx = fminf(pb[2], t0X);
        float rby = fminf(pb[3], t0Y);
        float w = fmaxf(rbx - ltx, 0.0f);
        float h = fmaxf(rby - lty, 0.0f);
        float inter = w * h;
        float a1 = (pb[2] - pb[0]) * (pb[3] - pb[1]);
        iou[b] = inter / (a1 + a2 - inter);
    }

    // jnp.argmax takes the FIRST max on ties -> strict '>' for box 1
    const int best = (iou[1] > iou[0]) ? 1 : 0;
    const float maxiou = iou[best];

    const float* pb = p + best * 5;
    const float* tb = g + best * 5;

    const float dx = pb[0] - tb[0];
    const float dy = pb[1] - tb[1];
    float lxy = m * (dx * dx + dy * dy);

    const float dw = sqrtf(pb[2]) - sqrtf(tb[2]);
    const float dh = sqrtf(pb[3]) - sqrtf(tb[3]);
    float lwh = m * (dw * dw + dh * dh);

    const float dobj = pb[4] - maxiou;
    float lobj = m * dobj * dobj;

    const float d4 = p[4] - g[4];
    const float d9 = p[9] - g[9];
    float lnoobj = nm * (d4 * d4 + d9 * d9);

    float cs = 0.0f;
    #pragma unroll
    for (int c = 10; c < 30; c++) {
        const float d = p[c] - g[c];
        cs += d * d;
    }
    float lcls = m * cs;

    // ---- Block reduction of 5 partials ----
    #pragma unroll
    for (int o = 16; o > 0; o >>= 1) {
        lxy    += __shfl_down_sync(0xffffffffu, lxy,    o);
        lwh    += __shfl_down_sync(0xffffffffu, lwh,    o);
        lobj   += __shfl_down_sync(0xffffffffu, lobj,   o);
        lnoobj += __shfl_down_sync(0xffffffffu, lnoobj, o);
        lcls   += __shfl_down_sync(0xffffffffu, lcls,   o);
    }
    const int wid  = tid >> 5;
    const int lane = tid & 31;
    if (lane == 0) {
        red[wid][0] = lxy;
        red[wid][1] = lwh;
        red[wid][2] = lobj;
        red[wid][3] = lnoobj;
        red[wid][4] = lcls;
    }
    __syncthreads();
    if (tid < 5) {
        float s = 0.0f;
        #pragma unroll
        for (int w = 0; w < THREADS / 32; w++) s += red[w][tid];
        atomicAdd(out + tid, s);
    }
}

extern "C" void kernel_launch(void* const* d_in, const int* in_sizes, int n_in,
                              void* d_out, int out_size) {
    const float* pred = (const float*)d_in[0];
    const float* tgt  = (const float*)d_in[1];
    float* out = (float*)d_out;

    cudaMemsetAsync(out, 0, (size_t)out_size * sizeof(float));
    yolo_loss_kernel<<<CELLS / CPB, THREADS>>>(pred, tgt, out);
}